// round 14
// baseline (speedup 1.0000x reference)
#include <cuda_runtime.h>

// Fixed problem shapes
#define NBATCH 8
#define NP 64
#define NV 32
#define ND 1626
#define NPAIR 813                    // dir pairs per tile
#define NTILE (NBATCH * NP)          // 512
#define NTHREADS 128
#define NBLK ((NTILE * NPAIR) / NTHREADS)   // 3252 exactly

__device__ __forceinline__ float fast_lg2(float x) {
    float r; asm("lg2.approx.ftz.f32 %0, %1;" : "=f"(r) : "f"(x)); return r;
}
__device__ __forceinline__ float fast_ex2(float x) {
    float r; asm("ex2.approx.ftz.f32 %0, %1;" : "=f"(r) : "f"(x)); return r;
}

__global__ __launch_bounds__(NTHREADS, 8) void spt_kernel(
    const float* __restrict__ vertices,    // (B,P,V,3)
    const float* __restrict__ smoothness,  // (B,P)
    float* __restrict__ out)
{
    __shared__ float sc1[30], ss1[30], sc2[59], ss2[59];
    __shared__ __align__(16) float s_x[2][NV], s_y[2][NV], s_z[2][NV];
    __shared__ __align__(16) float s_aos[2][NV * 3];
    __shared__ __align__(16) float4 s_cst[2][2];   // [0]={mx,my,mz,pm1} [1]={c0,invp,q,qLR}

    const int tid = threadIdx.x;
    const int wid = tid >> 5;
    const int lane = tid & 31;

    // ── Per-block fp32 sincos table. Angles formed in fp64 then cast (matches
    // numpy linspace nodes); sincosf is ~2e-7 rel accurate for all O(1)
    // entries. The 3 entries that are tiny fp64 residuals (cos ±pi/2, sin -pi)
    // are hardcoded to the exact fp64-cast constants.
    {
        const double PI = 3.141592653589793;
        if (tid < 30) {
            double th = (tid == 0)  ? -PI * 0.5
                      : (tid == 29) ?  PI * 0.5
                      : (double)tid * (PI / 29.0) + (-PI * 0.5);
            float s, c;
            sincosf((float)th, &s, &c);
            sc1[tid] = (tid == 0 || tid == 29) ? 6.123233995736766e-17f : c;
            ss1[tid] = s;
        } else if (tid < 89) {
            int i = tid - 30;
            double th = (i == 0) ? -PI : (double)i * (2.0 * PI / 58.0) + (-PI);
            float s, c;
            sincosf((float)th, &s, &c);
            sc2[i] = c;
            ss2[i] = (i == 0) ? -1.2246467991473532e-16f : s;
        }
    }

    const int f0 = blockIdx.x * NTHREADS;                 // global pair index base
    const int bp_first = f0 / NPAIR;
    const int bp_last  = (f0 + NTHREADS - 1) / NPAIR;
    const int ntiles   = bp_last - bp_first + 1;          // 1 or 2

    // Output sections (tuple flattened in reference order)
    float* const out_points = out;
    float* const out_dh     = out + (size_t)NBATCH * NP * ND * 3;
    float* const out_ov     = out + (size_t)NBATCH * NP * ND * 7;
    float* const out_re     = out_ov + NTILE;
    float* const out_mean   = out_re + NTILE;
    float* const out_lv     = out_mean + NTILE * 3;

    // ── Per-tile prep: warp w handles tile bp_first+w
    if (wid < ntiles) {
        const int bp = bp_first + wid;
        const float* vin = vertices + (size_t)bp * (NV * 3);
        if (lane < 24)
            reinterpret_cast<float4*>(s_aos[wid])[lane] =
                reinterpret_cast<const float4*>(vin)[lane];
        __syncwarp();

        const float x = s_aos[wid][lane * 3 + 0];
        const float y = s_aos[wid][lane * 3 + 1];
        const float z = s_aos[wid][lane * 3 + 2];

        float sx = x, sy = y, sz = z;
        #pragma unroll
        for (int o = 16; o > 0; o >>= 1) {
            sx += __shfl_xor_sync(0xFFFFFFFFu, sx, o);
            sy += __shfl_xor_sync(0xFFFFFFFFu, sy, o);
            sz += __shfl_xor_sync(0xFFFFFFFFu, sz, o);
        }
        const float mx = sx * (1.0f / 32.0f);
        const float my = sy * (1.0f / 32.0f);
        const float mz = sz * (1.0f / 32.0f);

        const float lvx = x - mx, lvy = y - my, lvz = z - mz;
        s_x[wid][lane] = lvx; s_y[wid][lane] = lvy; s_z[wid][lane] = lvz;

        float r2 = lvx * lvx + lvy * lvy + lvz * lvz;
        #pragma unroll
        for (int o = 16; o > 0; o >>= 1)
            r2 = fmaxf(r2, __shfl_xor_sync(0xFFFFFFFFu, r2, o));

        // This block owns the tile iff the tile's first pair lies in-range
        const int tile_start = bp * NPAIR;
        const bool owner = (tile_start >= f0) && (tile_start < f0 + NTHREADS);
        if (owner) {
            float* olv = out_lv + (size_t)bp * (NV * 3) + lane * 3;
            olv[0] = lvx; olv[1] = lvy; olv[2] = lvz;
        }
        if (lane == 0) {
            const float p    = smoothness[bp];
            const float pm1  = p - 1.0f;
            const float invp = 1.0f / p;
            const float q    = pm1 * invp;
            const float LR   = 0.5f * fast_lg2(r2);   // lg2(max ||lv||)
            s_cst[wid][0] = make_float4(mx, my, mz, pm1);
            s_cst[wid][1] = make_float4(-pm1 * LR, invp, q, q * LR);
            if (owner) {
                out_ov[bp] = 0.0f;
                out_re[bp] = 0.0f;
                out_mean[bp * 3 + 0] = mx;
                out_mean[bp * 3 + 1] = my;
                out_mean[bp * 3 + 2] = mz;
            }
        }
    }
    __syncthreads();

    const int f  = f0 + tid;                              // pair index
    const int bp = f / NPAIR;
    const int t  = bp - bp_first;
    const int d0 = (f - bp * NPAIR) * 2;                  // pair {d0, d0+1}

    // Assemble this thread's two directions from the trig table.
    // d0 is even and rows are 58 wide (even), so a pair never straddles rows;
    // d0 == 1624 is exactly the two poles.
    float DAx, DAy, DAz, DBx, DBy, DBz;
    if (d0 < 1624) {
        const int r  = d0 / 58;
        const int i2 = d0 - r * 58;
        const float C1 = sc1[r + 1], S1 = ss1[r + 1];
        DAx = C1 * sc2[i2];     DAy = C1 * ss2[i2];     DAz = S1;
        DBx = C1 * sc2[i2 + 1]; DBy = C1 * ss2[i2 + 1]; DBz = S1;
    } else {
        DAx = sc1[0]  * sc2[0]; DAy = sc1[0]  * ss2[0]; DAz = ss1[0];
        DBx = sc1[29] * sc2[0]; DBy = sc1[29] * ss2[0]; DBz = ss1[29];
    }

    const float4 cm = s_cst[t][0];   // mx,my,mz,pm1
    const float4 cp = s_cst[t][1];   // c0,invp,q,qLR
    const float pm1 = cm.w;
    const float c0  = cp.x;

    const float4* x4 = reinterpret_cast<const float4*>(s_x[t]);
    const float4* y4 = reinterpret_cast<const float4*>(s_y[t]);
    const float4* z4 = reinterpret_cast<const float4*>(s_z[t]);

    float ax0 = 0.f, ay0 = 0.f, az0 = 0.f;
    float ax1 = 0.f, ay1 = 0.f, az1 = 0.f;

    #pragma unroll
    for (int j = 0; j < NV / 4; j++) {
        float4 X = x4[j], Y = y4[j], Z = z4[j];
        #define VSTEP(C)                                                          \
        {                                                                         \
            float zA = fmaxf(fmaf(DAz, Z.C, fmaf(DAy, Y.C, DAx * X.C)), 0.f);     \
            float zB = fmaxf(fmaf(DBz, Z.C, fmaf(DBy, Y.C, DBx * X.C)), 0.f);     \
            float eA = fast_ex2(fmaf(pm1, fast_lg2(zA), c0));                     \
            float eB = fast_ex2(fmaf(pm1, fast_lg2(zB), c0));                     \
            ax0 = fmaf(eA, X.C, ax0); ax1 = fmaf(eB, X.C, ax1);                   \
            ay0 = fmaf(eA, Y.C, ay0); ay1 = fmaf(eB, Y.C, ay1);                   \
            az0 = fmaf(eA, Z.C, az0); az1 = fmaf(eB, Z.C, az1);                   \
        }
        VSTEP(x) VSTEP(y) VSTEP(z) VSTEP(w)
        #undef VSTEP
    }

    // S = d . a   (exact reassociation of sum(e*z))
    const float SA = fmaxf(fmaf(DAz, az0, fmaf(DAy, ay0, DAx * ax0)), 1e-35f);
    const float SB = fmaxf(fmaf(DBz, az1, fmaf(DBy, ay1, DBx * ax1)), 1e-35f);

    const float q = cp.z, qLR = cp.w;
    const float LSA = fast_lg2(SA);
    const float LSB = fast_lg2(SB);
    // scale = h^(1-p) rescaled; hout = scale * S  (since invp + q = 1)
    const float scaleA = fast_ex2(fmaf(-q, LSA, qLR));
    const float scaleB = fast_ex2(fmaf(-q, LSB, qLR));
    const float houtA  = scaleA * SA;
    const float houtB  = scaleB * SB;

    const float pAx = fmaf(ax0, scaleA, cm.x);
    const float pAy = fmaf(ay0, scaleA, cm.y);
    const float pAz = fmaf(az0, scaleA, cm.z);
    const float pBx = fmaf(ax1, scaleB, cm.x);
    const float pBy = fmaf(ay1, scaleB, cm.y);
    const float pBz = fmaf(az1, scaleB, cm.z);

    const size_t bd = (size_t)bp * ND + d0;
    float2* p2 = reinterpret_cast<float2*>(out_points + bd * 3);
    p2[0] = make_float2(pAx, pAy);
    p2[1] = make_float2(pAz, pBx);
    p2[2] = make_float2(pBy, pBz);

    float4* dh4 = reinterpret_cast<float4*>(out_dh) + bd;
    dh4[0] = make_float4(DAx, DAy, DAz, houtA);
    dh4[1] = make_float4(DBx, DBy, DBz, houtB);
}

extern "C" void kernel_launch(void* const* d_in, const int* in_sizes, int n_in,
                              void* d_out, int out_size) {
    const float* vertices   = (const float*)d_in[0];   // (8,64,32,3)
    const float* smoothness = (const float*)d_in[1];   // (8,64)
    float* out = (float*)d_out;

    spt_kernel<<<NBLK, NTHREADS>>>(vertices, smoothness, out);
}

// round 15
// speedup vs baseline: 1.1342x; 1.1342x over previous
#include <cuda_runtime.h>

// Fixed problem shapes
#define NBATCH 8
#define NP 64
#define NV 32
#define ND 1626
#define NPAIR 813                    // dir pairs per tile
#define NTILE (NBATCH * NP)          // 512
#define NTHREADS 256
#define NBLK ((NTILE * NPAIR) / NTHREADS)   // 512*813/256 = 1626 exactly

__device__ __forceinline__ float fast_lg2(float x) {
    float r; asm("lg2.approx.ftz.f32 %0, %1;" : "=f"(r) : "f"(x)); return r;
}
__device__ __forceinline__ float fast_ex2(float x) {
    float r; asm("ex2.approx.ftz.f32 %0, %1;" : "=f"(r) : "f"(x)); return r;
}

__global__ __launch_bounds__(NTHREADS, 4) void spt_kernel(
    const float* __restrict__ vertices,    // (B,P,V,3)
    const float* __restrict__ smoothness,  // (B,P)
    float* __restrict__ out)
{
    __shared__ float sc1[30], ss1[30], sc2[59], ss2[59];
    __shared__ __align__(16) float s_x[2][NV], s_y[2][NV], s_z[2][NV];
    __shared__ __align__(16) float s_aos[2][NV * 3];
    __shared__ __align__(16) float4 s_cst[2][2];   // [0]={mx,my,mz,pm1} [1]={c0,invp,q,qLR}

    const int tid = threadIdx.x;
    const int wid = tid >> 5;
    const int lane = tid & 31;

    const int f0 = blockIdx.x * NTHREADS;                 // global pair index base
    const int bp_first = f0 / NPAIR;
    const int bp_last  = (f0 + NTHREADS - 1) / NPAIR;
    const int ntiles   = bp_last - bp_first + 1;          // 1 or 2 (256 < 813)

    // Output sections (tuple flattened in reference order)
    float* const out_points = out;
    float* const out_dh     = out + (size_t)NBATCH * NP * ND * 3;
    float* const out_ov     = out + (size_t)NBATCH * NP * ND * 7;
    float* const out_re     = out_ov + NTILE;
    float* const out_mean   = out_re + NTILE;
    float* const out_lv     = out_mean + NTILE * 3;

    // ── Concurrent block prologue, one __syncthreads total:
    //    warps 0..1 : per-tile prep (vertices -> mean/local_v/constants)
    //    warps 2..4 : fp32 sincos table (angles formed with numpy's exact fp64
    //                 arithmetic then cast; 3 tiny fp64-residual entries
    //                 hardcoded — accuracy validated at rel_err 5.7e-7).
    if (wid < ntiles) {
        const int bp = bp_first + wid;
        const float* vin = vertices + (size_t)bp * (NV * 3);
        if (lane < 24)
            reinterpret_cast<float4*>(s_aos[wid])[lane] =
                reinterpret_cast<const float4*>(vin)[lane];
        __syncwarp();

        const float x = s_aos[wid][lane * 3 + 0];
        const float y = s_aos[wid][lane * 3 + 1];
        const float z = s_aos[wid][lane * 3 + 2];

        float sx = x, sy = y, sz = z;
        #pragma unroll
        for (int o = 16; o > 0; o >>= 1) {
            sx += __shfl_xor_sync(0xFFFFFFFFu, sx, o);
            sy += __shfl_xor_sync(0xFFFFFFFFu, sy, o);
            sz += __shfl_xor_sync(0xFFFFFFFFu, sz, o);
        }
        const float mx = sx * (1.0f / 32.0f);
        const float my = sy * (1.0f / 32.0f);
        const float mz = sz * (1.0f / 32.0f);

        const float lvx = x - mx, lvy = y - my, lvz = z - mz;
        s_x[wid][lane] = lvx; s_y[wid][lane] = lvy; s_z[wid][lane] = lvz;

        float r2 = lvx * lvx + lvy * lvy + lvz * lvz;
        #pragma unroll
        for (int o = 16; o > 0; o >>= 1)
            r2 = fmaxf(r2, __shfl_xor_sync(0xFFFFFFFFu, r2, o));

        // This block owns the tile iff the tile's first pair lies in-range
        const int tile_start = bp * NPAIR;
        const bool owner = (tile_start >= f0) && (tile_start < f0 + NTHREADS);
        if (owner) {
            float* olv = out_lv + (size_t)bp * (NV * 3) + lane * 3;
            olv[0] = lvx; olv[1] = lvy; olv[2] = lvz;
        }
        if (lane == 0) {
            const float p    = smoothness[bp];
            const float pm1  = p - 1.0f;
            const float invp = 1.0f / p;
            const float q    = pm1 * invp;
            const float LR   = 0.5f * fast_lg2(r2);   // lg2(max ||lv||)
            s_cst[wid][0] = make_float4(mx, my, mz, pm1);
            s_cst[wid][1] = make_float4(-pm1 * LR, invp, q, q * LR);
            if (owner) {
                out_ov[bp] = 0.0f;
                out_re[bp] = 0.0f;
                out_mean[bp * 3 + 0] = mx;
                out_mean[bp * 3 + 1] = my;
                out_mean[bp * 3 + 2] = mz;
            }
        }
    } else if (tid >= 64 && tid < 64 + 89) {
        const double PI = 3.141592653589793;
        const int k = tid - 64;
        if (k < 30) {
            double th = (k == 0)  ? -PI * 0.5
                      : (k == 29) ?  PI * 0.5
                      : (double)k * (PI / 29.0) + (-PI * 0.5);
            float s, c;
            sincosf((float)th, &s, &c);
            sc1[k] = (k == 0 || k == 29) ? 6.123233995736766e-17f : c;
            ss1[k] = s;
        } else {
            const int i = k - 30;
            double th = (i == 0) ? -PI : (double)i * (2.0 * PI / 58.0) + (-PI);
            float s, c;
            sincosf((float)th, &s, &c);
            sc2[i] = c;
            ss2[i] = (i == 0) ? -1.2246467991473532e-16f : s;
        }
    }
    __syncthreads();

    const int f  = f0 + tid;                              // pair index
    const int bp = f / NPAIR;
    const int t  = bp - bp_first;
    const int d0 = (f - bp * NPAIR) * 2;                  // pair {d0, d0+1}

    // Assemble this thread's two directions from the trig table.
    // d0 is even and rows are 58 wide, so a pair never straddles rows;
    // d0 == 1624 is exactly the two poles.
    float DAx, DAy, DAz, DBx, DBy, DBz;
    if (d0 < 1624) {
        const int r  = d0 / 58;
        const int i2 = d0 - r * 58;
        const float C1 = sc1[r + 1], S1 = ss1[r + 1];
        DAx = C1 * sc2[i2];     DAy = C1 * ss2[i2];     DAz = S1;
        DBx = C1 * sc2[i2 + 1]; DBy = C1 * ss2[i2 + 1]; DBz = S1;
    } else {
        DAx = sc1[0]  * sc2[0]; DAy = sc1[0]  * ss2[0]; DAz = ss1[0];
        DBx = sc1[29] * sc2[0]; DBy = sc1[29] * ss2[0]; DBz = ss1[29];
    }

    const float4 cm = s_cst[t][0];   // mx,my,mz,pm1
    const float4 cp = s_cst[t][1];   // c0,invp,q,qLR
    const float pm1 = cm.w;
    const float c0  = cp.x;

    const float4* x4 = reinterpret_cast<const float4*>(s_x[t]);
    const float4* y4 = reinterpret_cast<const float4*>(s_y[t]);
    const float4* z4 = reinterpret_cast<const float4*>(s_z[t]);

    float ax0 = 0.f, ay0 = 0.f, az0 = 0.f;
    float ax1 = 0.f, ay1 = 0.f, az1 = 0.f;

    #pragma unroll
    for (int j = 0; j < NV / 4; j++) {
        float4 X = x4[j], Y = y4[j], Z = z4[j];
        #define VSTEP(C)                                                          \
        {                                                                         \
            float zA = fmaxf(fmaf(DAz, Z.C, fmaf(DAy, Y.C, DAx * X.C)), 0.f);     \
            float zB = fmaxf(fmaf(DBz, Z.C, fmaf(DBy, Y.C, DBx * X.C)), 0.f);     \
            float eA = fast_ex2(fmaf(pm1, fast_lg2(zA), c0));                     \
            float eB = fast_ex2(fmaf(pm1, fast_lg2(zB), c0));                     \
            ax0 = fmaf(eA, X.C, ax0); ax1 = fmaf(eB, X.C, ax1);                   \
            ay0 = fmaf(eA, Y.C, ay0); ay1 = fmaf(eB, Y.C, ay1);                   \
            az0 = fmaf(eA, Z.C, az0); az1 = fmaf(eB, Z.C, az1);                   \
        }
        VSTEP(x) VSTEP(y) VSTEP(z) VSTEP(w)
        #undef VSTEP
    }

    // S = d . a   (exact reassociation of sum(e*z))
    const float SA = fmaxf(fmaf(DAz, az0, fmaf(DAy, ay0, DAx * ax0)), 1e-35f);
    const float SB = fmaxf(fmaf(DBz, az1, fmaf(DBy, ay1, DBx * ax1)), 1e-35f);

    const float q = cp.z, qLR = cp.w;
    const float LSA = fast_lg2(SA);
    const float LSB = fast_lg2(SB);
    // scale = ex2(qLR - q*LS); hout = ex2(invp*LS + qLR) = scale * S (invp+q=1)
    const float scaleA = fast_ex2(fmaf(-q, LSA, qLR));
    const float scaleB = fast_ex2(fmaf(-q, LSB, qLR));
    const float houtA  = scaleA * SA;
    const float houtB  = scaleB * SB;

    const float pAx = fmaf(ax0, scaleA, cm.x);
    const float pAy = fmaf(ay0, scaleA, cm.y);
    const float pAz = fmaf(az0, scaleA, cm.z);
    const float pBx = fmaf(ax1, scaleB, cm.x);
    const float pBy = fmaf(ay1, scaleB, cm.y);
    const float pBz = fmaf(az1, scaleB, cm.z);

    const size_t bd = (size_t)bp * ND + d0;
    float2* p2 = reinterpret_cast<float2*>(out_points + bd * 3);
    p2[0] = make_float2(pAx, pAy);
    p2[1] = make_float2(pAz, pBx);
    p2[2] = make_float2(pBy, pBz);

    float4* dh4 = reinterpret_cast<float4*>(out_dh) + bd;
    dh4[0] = make_float4(DAx, DAy, DAz, houtA);
    dh4[1] = make_float4(DBx, DBy, DBz, houtB);
}

extern "C" void kernel_launch(void* const* d_in, const int* in_sizes, int n_in,
                              void* d_out, int out_size) {
    const float* vertices   = (const float*)d_in[0];   // (8,64,32,3)
    const float* smoothness = (const float*)d_in[1];   // (8,64)
    float* out = (float*)d_out;

    spt_kernel<<<NBLK, NTHREADS>>>(vertices, smoothness, out);
}